// round 17
// baseline (speedup 1.0000x reference)
#include <cuda_runtime.h>
#include <cuda_bf16.h>

// Problem constants (fixed by the reference setup_inputs)
#define BB 64
#define SS 512
#define HH 768
#define WW 256      // MAX_WORD_LEN
#define WE 300
#define OUTW (HH + WE)   // 1068 floats
#define HV  (HH/4)       // 192 float4
#define WV  (WE/4)       // 75 float4
#define G   8            // words per CTA
#define NG  (WW/G)       // 32 groups per batch

// 8 words per 128-thread CTA (2048 CTAs ~ one wave). No smem, no barriers,
// no cross-word serial coupling: each warp loads all 512 sorted token_ids
// ONCE into registers (4 int4/lane) and computes a 9-field histogram
// (base=#<w0, h_k=#==w0+k) packed into 3x10-bit ints, 3 warp reduxes.
// All 9 segment bounds are then known upfront; the 8 per-word mean
// reductions are fully independent depth-4 dual-chain prefetches (MLP~8).
// Per-j cnt/wid are fetched with __shfl (no local-mem arrays).
// Token L1 traffic drops 8KB/word (R16) -> 0.25KB/word.
__global__ __launch_bounds__(128)
void embeddings_fused_kernel(const float* __restrict__ hidden,
                             const float* __restrict__ w2v,
                             const int*   __restrict__ token_ids,
                             const int*   __restrict__ word_ids,
                             float*       __restrict__ out)
{
    const int gi   = blockIdx.x;           // 0 .. 2047
    const int b    = gi >> 5;              // / NG
    const int w0   = (gi & (NG - 1)) << 3; // first word of group
    const int tid  = threadIdx.x;
    const int lane = tid & 31;

    // ---- lanes 0..7 hold the 8 word ids (coalesced 32B load) ----
    int wid_l = 0;
    if (lane < 8) wid_l = __ldg(word_ids + b * WW + w0 + lane);

    // ---- warp-private histogram over register-resident ids ----
    const int4* tb = reinterpret_cast<const int4*>(token_ids + b * SS);
    const int4 v0 = __ldg(tb + lane);
    const int4 v1 = __ldg(tb + lane + 32);
    const int4 v2 = __ldg(tb + lane + 64);
    const int4 v3 = __ldg(tb + lane + 96);

    int p0 = 0, p1 = 0, p2 = 0;
    #define HCOUNT(val) { int dd = (val) - w0;                                   \
        p0 += (dd < 0) + ((dd == 0) << 10) + ((dd == 1) << 20);                  \
        p1 += (dd == 2) + ((dd == 3) << 10) + ((dd == 4) << 20);                 \
        p2 += (dd == 5) + ((dd == 6) << 10) + ((dd == 7) << 20); }
    HCOUNT(v0.x) HCOUNT(v0.y) HCOUNT(v0.z) HCOUNT(v0.w)
    HCOUNT(v1.x) HCOUNT(v1.y) HCOUNT(v1.z) HCOUNT(v1.w)
    HCOUNT(v2.x) HCOUNT(v2.y) HCOUNT(v2.z) HCOUNT(v2.w)
    HCOUNT(v3.x) HCOUNT(v3.y) HCOUNT(v3.z) HCOUNT(v3.w)
    #undef HCOUNT
    p0 = __reduce_add_sync(0xffffffffu, p0);
    p1 = __reduce_add_sync(0xffffffffu, p1);
    p2 = __reduce_add_sync(0xffffffffu, p2);

    // lane l (0..7) exposes h_l for shfl; field index l+1 in [base,h0..h7]
    int h_l;
    {
        const int f  = lane + 1;
        const int Pw = (f < 3) ? p0 : ((f < 6) ? p1 : p2);
        const int sh = 10 * (f - ((f < 3) ? 0 : ((f < 6) ? 3 : 6)));
        h_l = (Pw >> sh) & 1023;
    }

    const float4* hb = reinterpret_cast<const float4*>(hidden + (size_t)b * SS * HH);
    const bool has2 = (tid < (HV - 128));   // tid < 64
    const bool hasw = (tid < WV);
    const float4 z = make_float4(0.f, 0.f, 0.f, 0.f);

    int lo = p0 & 1023;                     // lower_bound(w0)

    #pragma unroll 1
    for (int j = 0; j < G; ++j) {
        const int cnt = __shfl_sync(0xffffffffu, h_l, j);
        const int wid = __shfl_sync(0xffffffffu, wid_l, j);
        const float inv = (cnt > 0) ? (1.0f / (float)cnt) : 0.0f;

        // independent gather for this word (issues before hidden consume)
        float4 gv;
        if (hasw) {
            gv = __ldg(reinterpret_cast<const float4*>(w2v + (size_t)wid * WE) + tid);
        }

        const float4* c0 = hb + (size_t)lo * HV + tid;
        const float4* c1 = c0 + 128;
        float4 t0 = (cnt > 0) ? __ldcs(c0 + 0 * HV) : z;
        float4 t1 = (cnt > 1) ? __ldcs(c0 + 1 * HV) : z;
        float4 t2 = (cnt > 2) ? __ldcs(c0 + 2 * HV) : z;
        float4 t3 = (cnt > 3) ? __ldcs(c0 + 3 * HV) : z;
        float4 u0 = (has2 && cnt > 0) ? __ldcs(c1 + 0 * HV) : z;
        float4 u1 = (has2 && cnt > 1) ? __ldcs(c1 + 1 * HV) : z;
        float4 u2 = (has2 && cnt > 2) ? __ldcs(c1 + 2 * HV) : z;
        float4 u3 = (has2 && cnt > 3) ? __ldcs(c1 + 3 * HV) : z;

        float4 a0, a1;
        a0.x = (t0.x + t1.x) + (t2.x + t3.x);
        a0.y = (t0.y + t1.y) + (t2.y + t3.y);
        a0.z = (t0.z + t1.z) + (t2.z + t3.z);
        a0.w = (t0.w + t1.w) + (t2.w + t3.w);
        a1.x = (u0.x + u1.x) + (u2.x + u3.x);
        a1.y = (u0.y + u1.y) + (u2.y + u3.y);
        a1.z = (u0.z + u1.z) + (u2.z + u3.z);
        a1.w = (u0.w + u1.w) + (u2.w + u3.w);

        #pragma unroll 1
        for (int s = 4; s < cnt; ++s) {
            float4 q0 = __ldcs(c0 + (size_t)s * HV);
            a0.x += q0.x; a0.y += q0.y; a0.z += q0.z; a0.w += q0.w;
            if (has2) {
                float4 q1 = __ldcs(c1 + (size_t)s * HV);
                a1.x += q1.x; a1.y += q1.y; a1.z += q1.z; a1.w += q1.w;
            }
        }

        float4* orow = reinterpret_cast<float4*>(out + (size_t)(b * WW + w0 + j) * OUTW);
        a0.x *= inv; a0.y *= inv; a0.z *= inv; a0.w *= inv;
        __stcs(&orow[tid], a0);
        if (has2) {
            a1.x *= inv; a1.y *= inv; a1.z *= inv; a1.w *= inv;
            __stcs(&orow[tid + 128], a1);
        }
        if (hasw) {
            __stcs(&orow[HV + tid], gv);
        }

        lo += cnt;
    }
}

extern "C" void kernel_launch(void* const* d_in, const int* in_sizes, int n_in,
                              void* d_out, int out_size)
{
    // Identify inputs by element count (robust to ordering):
    //   hidden    : 64*512*768  = 25,165,824 (float32)
    //   w2v_table : 50000*300   = 15,000,000 (float32)
    //   token_ids : 64*512      = 32,768     (int32)
    //   word_ids  : 64*256      = 16,384     (int32)
    const float* hidden = nullptr;
    const float* w2v    = nullptr;
    const int*   tok    = nullptr;
    const int*   wids   = nullptr;
    for (int i = 0; i < n_in; ++i) {
        switch (in_sizes[i]) {
            case 25165824: hidden = (const float*)d_in[i]; break;
            case 15000000: w2v    = (const float*)d_in[i]; break;
            case 32768:    tok    = (const int*)d_in[i];   break;
            case 16384:    wids   = (const int*)d_in[i];   break;
            default: break;
        }
    }
    float* out = (float*)d_out;

    embeddings_fused_kernel<<<BB * NG, 128>>>(hidden, w2v, tok, wids, out);
}